// round 8
// baseline (speedup 1.0000x reference)
#include <cuda_runtime.h>
#include <cstdint>

#define BATCH 2048
#define NH    512
#define HC    256
#define ROWS  8            // rows per group / smem tile
#define TOPT  4            // samples per top item
#define IDXCAP 128

#define GRID  444          // 148 SMs * 3 CTAs, one wave
#define NQ    (HC + BATCH / TOPT)   // 256 bottom + 512 top = 768 items

// dynamic smem layout (floats)
#define S_LOG  (ROWS * NH)             // s_in: [0, 4096)
#define S_IDX  (S_LOG + ROWS * HC)     // s_log: [4096, 6144)
#define S_CNT  (S_IDX + IDXCAP)
#define S_POP  (S_CNT + 1)
#define SMEM_FLOATS (S_POP + 3)
#define SMEM_BYTES  (SMEM_FLOATS * 4)  // ~25.1 KB -> 3 CTAs/SM

__device__ float g_top_prob[BATCH];
__device__ float g_bot_prob[BATCH];
__device__ int   g_queue;   // work queue cursor (self-resetting)
__device__ int   g_done;    // CTA completion counter (self-resetting)

// ---------------- packed f32x2 helpers ----------------
__device__ __forceinline__ uint64_t pack2(float lo, float hi) {
    uint64_t d; asm("mov.b64 %0, {%1,%2};" : "=l"(d) : "f"(lo), "f"(hi)); return d;
}
__device__ __forceinline__ void unpack2(uint64_t v, float& lo, float& hi) {
    asm("mov.b64 {%0,%1}, %2;" : "=f"(lo), "=f"(hi) : "l"(v));
}
__device__ __forceinline__ uint64_t fma2(uint64_t a, uint64_t b, uint64_t c) {
    uint64_t d; asm("fma.rn.f32x2 %0, %1, %2, %3;" : "=l"(d) : "l"(a), "l"(b), "l"(c)); return d;
}
__device__ __forceinline__ void lds_v2u64(uint64_t& a, uint64_t& b, uint32_t addr) {
    asm volatile("ld.shared.v2.u64 {%0,%1}, [%2];" : "=l"(a), "=l"(b) : "r"(addr));
}

// ---------------------------------------------------------------------------
// 2-column GEMM body: SA rows x cols {c, c+128}, K-half of 256 per thread.
// One LDS.128 feeds 4 FFMA2 (2 cols x 2 k-pairs). W register ping-pong,
// prefetch distance 2 blocks of 4 k. No barriers in the mainloop.
// ---------------------------------------------------------------------------
template <int SA>
__device__ __forceinline__ void gemm2(
    const float* s_in_k, float* s_log,
    const float* __restrict__ wc,    // W + c + k0*HC  (col c, this k-half)
    int c, int half, float b0, float b1)
{
    uint64_t acc0[SA], acc1[SA];
#pragma unroll
    for (int s = 0; s < SA; s++) { acc0[s] = 0ull; acc1[s] = 0ull; }

    uint32_t sb = (uint32_t)__cvta_generic_to_shared(s_in_k);

    const int NBLK = (NH / 2) / 4;   // 64 blocks of 4 k
    float A0[4], A1[4], B0[4], B1[4];
#pragma unroll
    for (int i = 0; i < 4; i++) { A0[i] = wc[(size_t)i * HC]; A1[i] = wc[(size_t)i * HC + 128]; }
#pragma unroll
    for (int i = 0; i < 4; i++) { B0[i] = wc[(size_t)(4 + i) * HC]; B1[i] = wc[(size_t)(4 + i) * HC + 128]; }

    for (int ib = 0; ib < NBLK; ib += 2) {
        {   // block ib (buffer A), prefetch A <- ib+2
            uint64_t a01 = pack2(A0[0], A0[1]), a23 = pack2(A0[2], A0[3]);
            uint64_t c01 = pack2(A1[0], A1[1]), c23 = pack2(A1[2], A1[3]);
            int ip = (ib + 2 < NBLK) ? (ib + 2) : ib;
            const float* wp = wc + (size_t)ip * 4 * HC;
#pragma unroll
            for (int i = 0; i < 4; i++) { A0[i] = wp[(size_t)i * HC]; A1[i] = wp[(size_t)i * HC + 128]; }

            uint32_t a = sb + ib * 16;
#pragma unroll
            for (int s = 0; s < SA; s++) {
                uint64_t v01, v23;
                lds_v2u64(v01, v23, a);
                acc0[s] = fma2(v01, a01, acc0[s]);
                acc0[s] = fma2(v23, a23, acc0[s]);
                acc1[s] = fma2(v01, c01, acc1[s]);
                acc1[s] = fma2(v23, c23, acc1[s]);
                a += NH * 4;
            }
        }
        {   // block ib+1 (buffer B), prefetch B <- ib+3
            uint64_t a01 = pack2(B0[0], B0[1]), a23 = pack2(B0[2], B0[3]);
            uint64_t c01 = pack2(B1[0], B1[1]), c23 = pack2(B1[2], B1[3]);
            int ip = (ib + 3 < NBLK) ? (ib + 3) : (ib + 1);
            const float* wp = wc + (size_t)ip * 4 * HC;
#pragma unroll
            for (int i = 0; i < 4; i++) { B0[i] = wp[(size_t)i * HC]; B1[i] = wp[(size_t)i * HC + 128]; }

            uint32_t a = sb + (ib + 1) * 16;
#pragma unroll
            for (int s = 0; s < SA; s++) {
                uint64_t v01, v23;
                lds_v2u64(v01, v23, a);
                acc0[s] = fma2(v01, a01, acc0[s]);
                acc0[s] = fma2(v23, a23, acc0[s]);
                acc1[s] = fma2(v01, c01, acc1[s]);
                acc1[s] = fma2(v23, c23, acc1[s]);
                a += NH * 4;
            }
        }
    }

    float r0[SA], r1[SA];
#pragma unroll
    for (int s = 0; s < SA; s++) {
        float lo, hi;
        unpack2(acc0[s], lo, hi); r0[s] = lo + hi;
        unpack2(acc1[s], lo, hi); r1[s] = lo + hi;
    }
    if (half == 1) {
#pragma unroll
        for (int s = 0; s < SA; s++) {
            s_log[s * HC + c]       = r0[s];
            s_log[s * HC + c + 128] = r1[s];
        }
    }
    __syncthreads();
    if (half == 0) {
#pragma unroll
        for (int s = 0; s < SA; s++) {
            s_log[s * HC + c]       = r0[s] + s_log[s * HC + c]       + b0;
            s_log[s * HC + c + 128] = r1[s] + s_log[s * HC + c + 128] + b1;
        }
    }
    __syncthreads();
}

__device__ __forceinline__ void softmax_row(const float* row, int lane,
                                            float& m_out, float& sum_out)
{
    float m = -1e30f;
#pragma unroll
    for (int cc = lane; cc < HC; cc += 32) m = fmaxf(m, row[cc]);
#pragma unroll
    for (int o = 16; o > 0; o >>= 1) m = fmaxf(m, __shfl_xor_sync(0xffffffffu, m, o));
    float sum = 0.f;
#pragma unroll
    for (int cc = lane; cc < HC; cc += 32) sum += __expf(row[cc] - m);
#pragma unroll
    for (int o = 16; o > 0; o >>= 1) sum += __shfl_xor_sync(0xffffffffu, sum, o);
    m_out = m; sum_out = sum;
}

// ---------------------------------------------------------------------------
// Single-wave persistent kernel, 444 CTAs x 256 threads (3 CTAs/SM).
// Queue: item < 256 -> bottom parent (W streamed once from DRAM; row-groups
// of 8, later groups hit L2). item >= 256 -> top tile of 4 samples.
// Last CTA to finish writes out and resets counters.
// ---------------------------------------------------------------------------
__global__ __launch_bounds__(256, 3) void fused_kernel(
    const float* __restrict__ inputs, const int* __restrict__ labels,
    const int* __restrict__ parent,
    const float* __restrict__ topW, const float* __restrict__ topB,
    const float* __restrict__ botW, const float* __restrict__ botB,
    float* __restrict__ out)
{
    extern __shared__ float sm[];
    float* s_in  = sm;
    float* s_log = sm + S_LOG;
    int* s_idx = (int*)(sm + S_IDX);
    int* s_cnt = (int*)(sm + S_CNT);
    int* s_pop = (int*)(sm + S_POP);

    int tid = threadIdx.x;
    int c = tid & 127;                 // column pair {c, c+128}
    int half = tid >> 7;               // k-half
    int k0 = half * (NH / 2);
    int wid = tid >> 5, lane = tid & 31;

    for (;;) {
        __syncthreads();               // smem reuse across items
        if (tid == 0) *s_pop = atomicAdd(&g_queue, 1);
        __syncthreads();
        int item = *s_pop;
        if (item >= NQ) break;

        if (item >= HC) {
            // ----------------- TOP tile (4 samples) -----------------
            int b0 = (item - HC) * TOPT;
            const float4* gin = (const float4*)(inputs + (size_t)b0 * NH);
            float4* s4 = (float4*)s_in;
#pragma unroll
            for (int i = 0; i < TOPT * NH / 4 / 256; i++)
                s4[tid + i * 256] = gin[tid + i * 256];
            __syncthreads();

            gemm2<TOPT>(s_in + k0, s_log, topW + c + (size_t)k0 * HC, c, half,
                        topB[c], topB[c + 128]);

            if (wid < TOPT) {
                const float* row = s_log + wid * HC;
                float m, sum;
                softmax_row(row, lane, m, sum);
                if (lane == 0) {
                    int b = b0 + wid;
                    int p = parent[b];
                    g_top_prob[b] = __expf(row[p] - m) / sum;
                }
            }
        } else {
            // ----------------- BOTTOM parent -----------------
            int p = item;
            if (tid == 0) *s_cnt = 0;
            __syncthreads();
            for (int i = tid; i < BATCH; i += 256) {
                if (parent[i] == p) {
                    int q = atomicAdd(s_cnt, 1);
                    if (q < IDXCAP) s_idx[q] = i;
                }
            }
            __syncthreads();
            int n = min(*s_cnt, IDXCAP);
            if (n == 0) continue;

            const float* wc = botW + (size_t)p * NH * HC + c + (size_t)k0 * HC;
            float b0v = botB[(size_t)p * HC + c];
            float b1v = botB[(size_t)p * HC + c + 128];

            for (int c0 = 0; c0 < n; c0 += ROWS) {
                int S = min(ROWS, n - c0);
                __syncthreads();       // prev softmax done with s_log/s_in

                for (int i = tid; i < S * (NH / 4); i += 256) {
                    int s = i >> 7, q = i & 127;
                    int b = s_idx[c0 + s];
                    ((float4*)(s_in + s * NH))[q] = ((const float4*)(inputs + (size_t)b * NH))[q];
                }
                __syncthreads();

                if (S <= 4) gemm2<4>(s_in + k0, s_log, wc, c, half, b0v, b1v);
                else        gemm2<8>(s_in + k0, s_log, wc, c, half, b0v, b1v);

                if (wid < S) {
                    const float* row = s_log + wid * HC;
                    float m, sum;
                    softmax_row(row, lane, m, sum);
                    if (lane == 0) {
                        int b = s_idx[c0 + wid];
                        int l = labels[b];
                        g_bot_prob[b] = __expf(row[l] - m) / sum;
                    }
                }
            }
        }
    }

    // ----------------- last-CTA finalize -----------------
    __syncthreads();
    __threadfence();
    if (tid == 0) *s_pop = atomicAdd(&g_done, 1);
    __syncthreads();
    if (*s_pop == GRID - 1) {
        __threadfence();
#pragma unroll
        for (int i = 0; i < BATCH / 256; i++) {
            int b = tid + i * 256;
            out[b] = g_top_prob[b] * g_bot_prob[b];
        }
        __threadfence();
        if (tid == 0) { g_done = 0; g_queue = 0; }
    }
}

// ---------------------------------------------------------------------------
extern "C" void kernel_launch(void* const* d_in, const int* in_sizes, int n_in,
                              void* d_out, int out_size) {
    const float* inputs = (const float*)d_in[0];
    const int*   labels = (const int*)d_in[1];
    const int*   parent = (const int*)d_in[2];
    const float* topW   = (const float*)d_in[3];
    const float* topB   = (const float*)d_in[4];
    const float* botW   = (const float*)d_in[5];
    const float* botB   = (const float*)d_in[6];
    float* out = (float*)d_out;

    cudaFuncSetAttribute(fused_kernel,
                         cudaFuncAttributeMaxDynamicSharedMemorySize, SMEM_BYTES);

    fused_kernel<<<GRID, 256, SMEM_BYTES>>>(inputs, labels, parent,
                                            topW, topB, botW, botB, out);
}